// round 3
// baseline (speedup 1.0000x reference)
#include <cuda_runtime.h>
#include <math.h>

#define SQ 384
#define HDIM 768
#define NHEAD 12
#define DH 64
#define NC 24
#define QKW_I_STRIDE (NC*HDIM)   // 18432
#define OUT_I_STRIDE (NC*SQ)     // 9216

// ---------------- scratch (device globals; no allocation allowed) ----------
__device__ float g_Q[NHEAD*SQ*DH];
__device__ float g_K[NHEAD*SQ*DH];
__device__ float g_V[NHEAD*SQ*DH];
__device__ float g_kb[NHEAD*SQ];
__device__ float g_qkW[SQ*NC*HDIM];      // [i][c][e], c<12: qW(h=c), c>=12: kW(h=c-12)
__device__ float g_OUT[SQ*NC*SQ];        // [i][c][j], c<12: c2p[h,i,j]; c>=12: p2c pre-transpose
__device__ float g_C2C[NHEAD*SQ*SQ];     // [h][i][j]
__device__ float g_S[NHEAD*SQ*SQ];       // scores
__device__ float g_P[NHEAD*SQ*SQ];       // probs

__device__ __forceinline__ float2 ffma2(float2 a, float2 b, float2 c) {
    unsigned long long ua = *reinterpret_cast<unsigned long long*>(&a);
    unsigned long long ub = *reinterpret_cast<unsigned long long*>(&b);
    unsigned long long uc = *reinterpret_cast<unsigned long long*>(&c);
    unsigned long long ud;
    asm("fma.rn.f32x2 %0, %1, %2, %3;" : "=l"(ud) : "l"(ua), "l"(ub), "l"(uc));
    return *reinterpret_cast<float2*>(&ud);
}

// ================= K1: QKV projections ====================================
__global__ void k1_qkv(const float* __restrict__ hidden,
                       const float* __restrict__ Wq, const float* __restrict__ bq,
                       const float* __restrict__ Wk, const float* __restrict__ bk,
                       const float* __restrict__ Wv, const float* __restrict__ bv)
{
    __shared__ float2 A2[16*65];
    __shared__ float  Bs[16*64];
    int z = blockIdx.z;
    const float* W = (z==0) ? Wq : (z==1) ? Wk : Wv;
    const float* b = (z==0) ? bq : (z==1) ? bk : bv;
    float* outp    = (z==0) ? g_Q : (z==1) ? g_K : g_V;
    int h  = blockIdx.x;
    int i0 = blockIdx.y * 64;
    int tid = threadIdx.x;
    int ix = tid & 15, iy = tid >> 4;

    float2 acc[4][2];
    #pragma unroll
    for (int u = 0; u < 4; ++u) { acc[u][0] = make_float2(0.f,0.f); acc[u][1] = make_float2(0.f,0.f); }

    for (int k0 = 0; k0 < HDIM; k0 += 16) {
        __syncthreads();
        #pragma unroll
        for (int p = 0; p < 4; ++p) {
            int idx = tid + p*256;
            int kk = idx & 15, r = idx >> 4;
            float v = hidden[(i0 + r)*HDIM + k0 + kk];
            A2[kk*65 + r] = make_float2(v, v);
        }
        #pragma unroll
        for (int p = 0; p < 4; ++p) {
            int idx = tid + p*256;
            int nn = idx & 63, kk = idx >> 6;
            Bs[kk*64 + nn] = W[(k0 + kk)*HDIM + h*64 + nn];
        }
        __syncthreads();
        #pragma unroll
        for (int kk = 0; kk < 16; ++kk) {
            float2 b0 = *(const float2*)&Bs[kk*64 + ix*4];
            float2 b1 = *(const float2*)&Bs[kk*64 + ix*4 + 2];
            #pragma unroll
            for (int u = 0; u < 4; ++u) {
                float2 a = A2[kk*65 + iy*4 + u];
                acc[u][0] = ffma2(a, b0, acc[u][0]);
                acc[u][1] = ffma2(a, b1, acc[u][1]);
            }
        }
    }
    int nb = h*64 + ix*4;
    float b0 = b[nb], b1 = b[nb+1], b2 = b[nb+2], b3 = b[nb+3];
    #pragma unroll
    for (int u = 0; u < 4; ++u) {
        int i = i0 + iy*4 + u;
        float* o = outp + (h*SQ + i)*DH + ix*4;
        o[0] = acc[u][0].x + b0;
        o[1] = acc[u][0].y + b1;
        o[2] = acc[u][1].x + b2;
        o[3] = acc[u][1].y + b3;
    }
}

// ================= K1b: kb[h][j] = k[h,j,:].bpq_h =========================
__global__ void k1b_kb(const float* __restrict__ bpq)
{
    int h = blockIdx.x, j = threadIdx.x;
    const float* kp = g_K + (h*SQ + j)*DH;
    const float* bp = bpq + h*64;
    float s = 0.f;
    #pragma unroll 8
    for (int d = 0; d < DH; ++d) s += kp[d]*bp[d];
    g_kb[h*SQ + j] = s;
}

// ================= K2: qkW[i][c][e] =======================================
__global__ void k2_qkw(const float* __restrict__ Wpk, const float* __restrict__ Wpq)
{
    __shared__ float2 A2[64*33];
    __shared__ float  BsT[64*66];
    int c = blockIdx.z;
    int h = (c < 12) ? c : c - 12;
    const float* Asrc = (c < 12) ? g_Q : g_K;
    const float* Wp   = (c < 12) ? Wpk : Wpq;
    int e0 = blockIdx.x * 64;
    int i0 = blockIdx.y * 32;
    int tid = threadIdx.x;

    #pragma unroll
    for (int p = 0; p < 8; ++p) {
        int idx = tid + p*256;
        int dd = idx & 63, ii = idx >> 6;
        float v = Asrc[(h*SQ + i0 + ii)*DH + dd];
        A2[dd*33 + ii] = make_float2(v, v);
    }
    #pragma unroll
    for (int p = 0; p < 16; ++p) {
        int idx = tid + p*256;
        int dd = idx & 63, ee = idx >> 6;
        BsT[dd*66 + ee] = Wp[(e0 + ee)*HDIM + h*64 + dd];
    }
    __syncthreads();

    int dx = tid & 15, iy = tid >> 4;
    float2 acc[2][2];
    acc[0][0]=make_float2(0,0); acc[0][1]=make_float2(0,0);
    acc[1][0]=make_float2(0,0); acc[1][1]=make_float2(0,0);
    #pragma unroll 16
    for (int dd = 0; dd < 64; ++dd) {
        float2 a0 = A2[dd*33 + iy*2];
        float2 a1 = A2[dd*33 + iy*2 + 1];
        float2 b0 = *(const float2*)&BsT[dd*66 + dx*4];
        float2 b1 = *(const float2*)&BsT[dd*66 + dx*4 + 2];
        acc[0][0] = ffma2(a0, b0, acc[0][0]);
        acc[0][1] = ffma2(a0, b1, acc[0][1]);
        acc[1][0] = ffma2(a1, b0, acc[1][0]);
        acc[1][1] = ffma2(a1, b1, acc[1][1]);
    }
    #pragma unroll
    for (int r = 0; r < 2; ++r) {
        float* o = g_qkW + (size_t)(i0 + iy*2 + r)*QKW_I_STRIDE + c*HDIM + e0 + dx*4;
        *(float2*)o       = acc[r][0];
        *(float2*)(o + 2) = acc[r][1];
    }
}

// ================= K2b: c2c[h][i][j] ======================================
__global__ void k2b_c2c()
{
    __shared__ float2 A2[16*65];
    __shared__ float  Bs[16*66];
    int h  = blockIdx.z;
    int i0 = blockIdx.y * 64;
    int j0 = blockIdx.x * 64;
    int tid = threadIdx.x;
    int ix = tid & 15, iy = tid >> 4;

    float2 acc[4][2];
    #pragma unroll
    for (int u = 0; u < 4; ++u) { acc[u][0] = make_float2(0.f,0.f); acc[u][1] = make_float2(0.f,0.f); }

    for (int k0 = 0; k0 < DH; k0 += 16) {
        __syncthreads();
        #pragma unroll
        for (int p = 0; p < 4; ++p) {
            int idx = tid + p*256;
            int kk = idx & 15, r = idx >> 4;
            float v = g_Q[(h*SQ + i0 + r)*DH + k0 + kk];
            A2[kk*65 + r] = make_float2(v, v);
        }
        #pragma unroll
        for (int p = 0; p < 4; ++p) {
            int idx = tid + p*256;
            int kk = idx & 15, jj = idx >> 4;
            Bs[kk*66 + jj] = g_K[(h*SQ + j0 + jj)*DH + k0 + kk];
        }
        __syncthreads();
        #pragma unroll
        for (int kk = 0; kk < 16; ++kk) {
            float2 b0 = *(const float2*)&Bs[kk*66 + ix*4];
            float2 b1 = *(const float2*)&Bs[kk*66 + ix*4 + 2];
            #pragma unroll
            for (int u = 0; u < 4; ++u) {
                float2 a = A2[kk*65 + iy*4 + u];
                acc[u][0] = ffma2(a, b0, acc[u][0]);
                acc[u][1] = ffma2(a, b1, acc[u][1]);
            }
        }
    }
    #pragma unroll
    for (int u = 0; u < 4; ++u) {
        float* o = g_C2C + ((size_t)h*SQ + i0 + iy*4 + u)*SQ + j0 + ix*4;
        *(float2*)o       = acc[u][0];
        *(float2*)(o + 2) = acc[u][1];
    }
}

// ================= K3: stream pos_emb once (double-buffered) ==============
// CTA i: OUT[i][c][j] = sum_e pos[i,j,e] * qkW[i][c][e]
// e-chunk = 8, ping-pong SMEM, 1 barrier per chunk.
#define EC 8
#define NCH (HDIM/EC)       // 96
#define APITCH 388          // floats per ee-row (384 + pad, 8B-aligned rows)

__global__ void __launch_bounds__(128) k3_pos(const float* __restrict__ pos)
{
    __shared__ float  As[2][EC*APITCH];   // [buf][ee][j]   12.1KB each
    __shared__ float2 Ws2[2][EC*24];      // [buf][ee][c]   duplicated
    int i = blockIdx.x;
    int tid = threadIdx.x;
    int cg = tid & 3, jg = tid >> 2;

    const float* posi = pos + (size_t)i * (SQ*HDIM);
    const float* wsrc = g_qkW + (size_t)i * QKW_I_STRIDE;

    float2 acc[6][6];
    #pragma unroll
    for (int a = 0; a < 6; ++a)
        #pragma unroll
        for (int b = 0; b < 6; ++b) acc[a][b] = make_float2(0.f, 0.f);

    // per-thread load slots: 384j x 2 float4 (8 e) = 768 float4 / 128 thr = 6
    // idx = tid + p*128 ; j = idx>>1 ; q4 = idx&1
    float4 r[6];
    float  wv[2];

    // ---- prologue: chunk 0 ----
    #pragma unroll
    for (int p = 0; p < 6; ++p) {
        int idx = tid + p*128;
        int j = idx >> 1, q4 = idx & 1;
        r[p] = *(const float4*)(posi + (size_t)j*HDIM + q4*4);
    }
    #pragma unroll
    for (int p = 0; p < 2; ++p) {
        int idx = tid + p*128;            // 0..191 valid
        if (idx < EC*24) wv[p] = wsrc[(idx >> 3)*HDIM + (idx & 7)];
    }
    #pragma unroll
    for (int p = 0; p < 6; ++p) {
        int idx = tid + p*128;
        int j = idx >> 1, eb = (idx & 1)*4;
        As[0][(eb+0)*APITCH + j] = r[p].x;
        As[0][(eb+1)*APITCH + j] = r[p].y;
        As[0][(eb+2)*APITCH + j] = r[p].z;
        As[0][(eb+3)*APITCH + j] = r[p].w;
    }
    #pragma unroll
    for (int p = 0; p < 2; ++p) {
        int idx = tid + p*128;
        if (idx < EC*24) Ws2[0][(idx & 7)*24 + (idx >> 3)] = make_float2(wv[p], wv[p]);
    }
    __syncthreads();

    for (int ch = 0; ch < NCH; ++ch) {
        int cur = ch & 1, nxt = cur ^ 1;
        // prefetch next chunk into registers (hidden under compute)
        if (ch + 1 < NCH) {
            int e0 = (ch + 1) * EC;
            #pragma unroll
            for (int p = 0; p < 6; ++p) {
                int idx = tid + p*128;
                int j = idx >> 1, q4 = idx & 1;
                r[p] = *(const float4*)(posi + (size_t)j*HDIM + e0 + q4*4);
            }
            #pragma unroll
            for (int p = 0; p < 2; ++p) {
                int idx = tid + p*128;
                if (idx < EC*24) wv[p] = wsrc[(idx >> 3)*HDIM + e0 + (idx & 7)];
            }
        }
        // compute on current buffer
        #pragma unroll
        for (int ee = 0; ee < EC; ++ee) {
            float2 a[6];
            const float* arow = &As[cur][ee*APITCH + jg*12];
            #pragma unroll
            for (int b = 0; b < 6; ++b) a[b] = *(const float2*)&arow[2*b];
            #pragma unroll
            for (int u = 0; u < 6; ++u) {
                float2 w = Ws2[cur][ee*24 + cg*6 + u];
                #pragma unroll
                for (int b = 0; b < 6; ++b)
                    acc[u][b] = ffma2(a[b], w, acc[u][b]);
            }
        }
        // stage next chunk
        if (ch + 1 < NCH) {
            #pragma unroll
            for (int p = 0; p < 6; ++p) {
                int idx = tid + p*128;
                int j = idx >> 1, eb = (idx & 1)*4;
                As[nxt][(eb+0)*APITCH + j] = r[p].x;
                As[nxt][(eb+1)*APITCH + j] = r[p].y;
                As[nxt][(eb+2)*APITCH + j] = r[p].z;
                As[nxt][(eb+3)*APITCH + j] = r[p].w;
            }
            #pragma unroll
            for (int p = 0; p < 2; ++p) {
                int idx = tid + p*128;
                if (idx < EC*24) Ws2[nxt][(idx & 7)*24 + (idx >> 3)] = make_float2(wv[p], wv[p]);
            }
        }
        __syncthreads();
    }

    #pragma unroll
    for (int u = 0; u < 6; ++u) {
        int c = cg*6 + u;
        float* o = g_OUT + (size_t)i*OUT_I_STRIDE + c*SQ + jg*12;
        #pragma unroll
        for (int b = 0; b < 6; ++b)
            *(float2*)(o + 2*b) = acc[u][b];
    }
}

// ================= K3b: assemble scores (incl. p2c transpose) =============
__global__ void k3b_scores(const float* __restrict__ mask)
{
    __shared__ float sh[32*33];
    int h  = blockIdx.z;
    int i0 = blockIdx.y * 32;
    int j0 = blockIdx.x * 32;
    int tid = threadIdx.x;
    #pragma unroll
    for (int p = 0; p < 4; ++p) {
        int idx = tid + p*256;
        int ti = idx & 31, tj = idx >> 5;
        sh[tj*33 + ti] = g_OUT[(size_t)(j0 + tj)*OUT_I_STRIDE + (12 + h)*SQ + i0 + ti];
    }
    __syncthreads();
    #pragma unroll
    for (int p = 0; p < 4; ++p) {
        int idx = tid + p*256;
        int jj = idx & 31, ii = idx >> 5;
        int i = i0 + ii, j = j0 + jj;
        float v = g_C2C[((size_t)h*SQ + i)*SQ + j]
                + g_OUT[(size_t)i*OUT_I_STRIDE + h*SQ + j]
                + sh[jj*33 + ii]
                + g_kb[h*SQ + j];
        g_S[((size_t)h*SQ + i)*SQ + j] = v * 0.125f + mask[j];
    }
}

// ================= K4: softmax ============================================
__global__ void k4_softmax()
{
    __shared__ float red[4];
    int row = blockIdx.x;
    int tid = threadIdx.x;
    const float* s = g_S + (size_t)row*SQ;
    float x0 = s[tid], x1 = s[tid+128], x2 = s[tid+256];
    float m = fmaxf(x0, fmaxf(x1, x2));
    #pragma unroll
    for (int o = 16; o; o >>= 1) m = fmaxf(m, __shfl_xor_sync(0xffffffffu, m, o));
    if ((tid & 31) == 0) red[tid >> 5] = m;
    __syncthreads();
    m = fmaxf(fmaxf(red[0], red[1]), fmaxf(red[2], red[3]));
    float e0 = __expf(x0 - m), e1 = __expf(x1 - m), e2 = __expf(x2 - m);
    float ss = e0 + e1 + e2;
    #pragma unroll
    for (int o = 16; o; o >>= 1) ss += __shfl_xor_sync(0xffffffffu, ss, o);
    __syncthreads();
    if ((tid & 31) == 0) red[tid >> 5] = ss;
    __syncthreads();
    float inv = 1.f / (red[0] + red[1] + red[2] + red[3]);
    float* p = g_P + (size_t)row*SQ;
    p[tid] = e0*inv; p[tid+128] = e1*inv; p[tid+256] = e2*inv;
}

// ================= K5: context = P @ V, write output ======================
__global__ void k5_pv(float* __restrict__ out)
{
    __shared__ float2 A2[16*65];
    __shared__ float  Bs[16*64];
    int h  = blockIdx.y;
    int i0 = blockIdx.x * 64;
    int tid = threadIdx.x;
    int ix = tid & 15, iy = tid >> 4;

    float2 acc[4][2];
    #pragma unroll
    for (int u = 0; u < 4; ++u) { acc[u][0] = make_float2(0.f,0.f); acc[u][1] = make_float2(0.f,0.f); }

    for (int k0 = 0; k0 < SQ; k0 += 16) {
        __syncthreads();
        #pragma unroll
        for (int p = 0; p < 4; ++p) {
            int idx = tid + p*256;
            int kk = idx & 15, r = idx >> 4;
            float v = g_P[((size_t)h*SQ + i0 + r)*SQ + k0 + kk];
            A2[kk*65 + r] = make_float2(v, v);
        }
        #pragma unroll
        for (int p = 0; p < 4; ++p) {
            int idx = tid + p*256;
            int nn = idx & 63, kk = idx >> 6;
            Bs[kk*64 + nn] = g_V[(h*SQ + k0 + kk)*DH + nn];
        }
        __syncthreads();
        #pragma unroll
        for (int kk = 0; kk < 16; ++kk) {
            float2 b0 = *(const float2*)&Bs[kk*64 + ix*4];
            float2 b1 = *(const float2*)&Bs[kk*64 + ix*4 + 2];
            #pragma unroll
            for (int u = 0; u < 4; ++u) {
                float2 a = A2[kk*65 + iy*4 + u];
                acc[u][0] = ffma2(a, b0, acc[u][0]);
                acc[u][1] = ffma2(a, b1, acc[u][1]);
            }
        }
    }
    #pragma unroll
    for (int u = 0; u < 4; ++u) {
        int i = i0 + iy*4 + u;
        float* o = out + (size_t)i*HDIM + h*64 + ix*4;
        *(float2*)o       = acc[u][0];
        *(float2*)(o + 2) = acc[u][1];
    }
}

// ================= launch =================================================
extern "C" void kernel_launch(void* const* d_in, const int* in_sizes, int n_in,
                              void* d_out, int out_size)
{
    const float* hidden = (const float*)d_in[0];
    const float* mask   = (const float*)d_in[1];
    const float* pos    = (const float*)d_in[2];
    const float* Wq  = (const float*)d_in[3];
    const float* bq  = (const float*)d_in[4];
    const float* Wk  = (const float*)d_in[5];
    const float* bk  = (const float*)d_in[6];
    const float* Wv  = (const float*)d_in[7];
    const float* bv  = (const float*)d_in[8];
    const float* Wpk = (const float*)d_in[9];
    // d_in[10] = bpk: constant over j -> softmax-invariant -> exactly cancels
    const float* Wpq = (const float*)d_in[11];
    const float* bpq = (const float*)d_in[12];
    float* out = (float*)d_out;

    k1_qkv<<<dim3(12, 6, 3), 256>>>(hidden, Wq, bq, Wk, bk, Wv, bv);
    k1b_kb<<<12, 384>>>(bpq);
    k2_qkw<<<dim3(12, 12, 24), 256>>>(Wpk, Wpq);
    k2b_c2c<<<dim3(6, 6, 12), 256>>>();
    k3_pos<<<384, 128>>>(pos);
    k3b_scores<<<dim3(12, 12, 12), 256>>>(mask);
    k4_softmax<<<12*SQ, 128>>>();
    k5_pv<<<dim3(6, 12), 256>>>(out);
}

// round 4
// speedup vs baseline: 1.2342x; 1.2342x over previous
#include <cuda_runtime.h>
#include <math.h>

#define SQ 384
#define HDIM 768
#define NHEAD 12
#define DH 64
#define NC 24
#define QKW_I_STRIDE (NC*HDIM)   // 18432
#define OUT_I_STRIDE (NC*SQ)     // 9216

// ---------------- scratch (device globals; no allocation allowed) ----------
__device__ float g_Q[NHEAD*SQ*DH];
__device__ float g_K[NHEAD*SQ*DH];
__device__ float g_V[NHEAD*SQ*DH];
__device__ float g_kb[NHEAD*SQ];
__device__ float g_qkW[SQ*NC*HDIM];      // [i][c][e], c<12: qW(h=c), c>=12: kW(h=c-12)
__device__ float g_OUT[SQ*NC*SQ];        // [i][c][j]
__device__ float g_C2C[NHEAD*SQ*SQ];     // [h][i][j]
__device__ float g_S[NHEAD*SQ*SQ];       // scores
__device__ float g_P[NHEAD*SQ*SQ];       // probs

__device__ __forceinline__ float2 ffma2(float2 a, float2 b, float2 c) {
    unsigned long long ua = *reinterpret_cast<unsigned long long*>(&a);
    unsigned long long ub = *reinterpret_cast<unsigned long long*>(&b);
    unsigned long long uc = *reinterpret_cast<unsigned long long*>(&c);
    unsigned long long ud;
    asm("fma.rn.f32x2 %0, %1, %2, %3;" : "=l"(ud) : "l"(ua), "l"(ub), "l"(uc));
    return *reinterpret_cast<float2*>(&ud);
}

__device__ __forceinline__ void mma_tf32(float* d, unsigned a0, unsigned a1,
                                         unsigned a2, unsigned a3,
                                         unsigned b0, unsigned b1) {
    asm volatile(
        "mma.sync.aligned.m16n8k8.row.col.f32.tf32.tf32.f32 "
        "{%0,%1,%2,%3}, {%4,%5,%6,%7}, {%8,%9}, {%0,%1,%2,%3};"
        : "+f"(d[0]), "+f"(d[1]), "+f"(d[2]), "+f"(d[3])
        : "r"(a0), "r"(a1), "r"(a2), "r"(a3), "r"(b0), "r"(b1));
}

// ================= K1: QKV projections ====================================
__global__ void k1_qkv(const float* __restrict__ hidden,
                       const float* __restrict__ Wq, const float* __restrict__ bq,
                       const float* __restrict__ Wk, const float* __restrict__ bk,
                       const float* __restrict__ Wv, const float* __restrict__ bv)
{
    __shared__ float2 A2[16*65];
    __shared__ float  Bs[16*64];
    int z = blockIdx.z;
    const float* W = (z==0) ? Wq : (z==1) ? Wk : Wv;
    const float* b = (z==0) ? bq : (z==1) ? bk : bv;
    float* outp    = (z==0) ? g_Q : (z==1) ? g_K : g_V;
    int h  = blockIdx.x;
    int i0 = blockIdx.y * 64;
    int tid = threadIdx.x;
    int ix = tid & 15, iy = tid >> 4;

    float2 acc[4][2];
    #pragma unroll
    for (int u = 0; u < 4; ++u) { acc[u][0] = make_float2(0.f,0.f); acc[u][1] = make_float2(0.f,0.f); }

    for (int k0 = 0; k0 < HDIM; k0 += 16) {
        __syncthreads();
        #pragma unroll
        for (int p = 0; p < 4; ++p) {
            int idx = tid + p*256;
            int kk = idx & 15, r = idx >> 4;
            float v = hidden[(i0 + r)*HDIM + k0 + kk];
            A2[kk*65 + r] = make_float2(v, v);
        }
        #pragma unroll
        for (int p = 0; p < 4; ++p) {
            int idx = tid + p*256;
            int nn = idx & 63, kk = idx >> 6;
            Bs[kk*64 + nn] = W[(k0 + kk)*HDIM + h*64 + nn];
        }
        __syncthreads();
        #pragma unroll
        for (int kk = 0; kk < 16; ++kk) {
            float2 b0 = *(const float2*)&Bs[kk*64 + ix*4];
            float2 b1 = *(const float2*)&Bs[kk*64 + ix*4 + 2];
            #pragma unroll
            for (int u = 0; u < 4; ++u) {
                float2 a = A2[kk*65 + iy*4 + u];
                acc[u][0] = ffma2(a, b0, acc[u][0]);
                acc[u][1] = ffma2(a, b1, acc[u][1]);
            }
        }
    }
    int nb = h*64 + ix*4;
    float b0 = b[nb], b1 = b[nb+1], b2 = b[nb+2], b3 = b[nb+3];
    #pragma unroll
    for (int u = 0; u < 4; ++u) {
        int i = i0 + iy*4 + u;
        float* o = outp + (h*SQ + i)*DH + ix*4;
        o[0] = acc[u][0].x + b0;
        o[1] = acc[u][0].y + b1;
        o[2] = acc[u][1].x + b2;
        o[3] = acc[u][1].y + b3;
    }
}

// ================= K1b: kb[h][j] = k[h,j,:].bpq_h =========================
__global__ void k1b_kb(const float* __restrict__ bpq)
{
    int h = blockIdx.x, j = threadIdx.x;
    const float* kp = g_K + (h*SQ + j)*DH;
    const float* bp = bpq + h*64;
    float s = 0.f;
    #pragma unroll 8
    for (int d = 0; d < DH; ++d) s += kp[d]*bp[d];
    g_kb[h*SQ + j] = s;
}

// ================= K2: qkW[i][c][e] =======================================
__global__ void k2_qkw(const float* __restrict__ Wpk, const float* __restrict__ Wpq)
{
    __shared__ float2 A2[64*33];
    __shared__ float  BsT[64*66];
    int c = blockIdx.z;
    int h = (c < 12) ? c : c - 12;
    const float* Asrc = (c < 12) ? g_Q : g_K;
    const float* Wp   = (c < 12) ? Wpk : Wpq;
    int e0 = blockIdx.x * 64;
    int i0 = blockIdx.y * 32;
    int tid = threadIdx.x;

    #pragma unroll
    for (int p = 0; p < 8; ++p) {
        int idx = tid + p*256;
        int dd = idx & 63, ii = idx >> 6;
        float v = Asrc[(h*SQ + i0 + ii)*DH + dd];
        A2[dd*33 + ii] = make_float2(v, v);
    }
    #pragma unroll
    for (int p = 0; p < 16; ++p) {
        int idx = tid + p*256;
        int dd = idx & 63, ee = idx >> 6;
        BsT[dd*66 + ee] = Wp[(e0 + ee)*HDIM + h*64 + dd];
    }
    __syncthreads();

    int dx = tid & 15, iy = tid >> 4;
    float2 acc[2][2];
    acc[0][0]=make_float2(0,0); acc[0][1]=make_float2(0,0);
    acc[1][0]=make_float2(0,0); acc[1][1]=make_float2(0,0);
    #pragma unroll 16
    for (int dd = 0; dd < 64; ++dd) {
        float2 a0 = A2[dd*33 + iy*2];
        float2 a1 = A2[dd*33 + iy*2 + 1];
        float2 b0 = *(const float2*)&BsT[dd*66 + dx*4];
        float2 b1 = *(const float2*)&BsT[dd*66 + dx*4 + 2];
        acc[0][0] = ffma2(a0, b0, acc[0][0]);
        acc[0][1] = ffma2(a0, b1, acc[0][1]);
        acc[1][0] = ffma2(a1, b0, acc[1][0]);
        acc[1][1] = ffma2(a1, b1, acc[1][1]);
    }
    #pragma unroll
    for (int r = 0; r < 2; ++r) {
        float* o = g_qkW + (size_t)(i0 + iy*2 + r)*QKW_I_STRIDE + c*HDIM + e0 + dx*4;
        *(float2*)o       = acc[r][0];
        *(float2*)(o + 2) = acc[r][1];
    }
}

// ================= K2b: c2c[h][i][j] ======================================
__global__ void k2b_c2c()
{
    __shared__ float2 A2[16*65];
    __shared__ float  Bs[16*66];
    int h  = blockIdx.z;
    int i0 = blockIdx.y * 64;
    int j0 = blockIdx.x * 64;
    int tid = threadIdx.x;
    int ix = tid & 15, iy = tid >> 4;

    float2 acc[4][2];
    #pragma unroll
    for (int u = 0; u < 4; ++u) { acc[u][0] = make_float2(0.f,0.f); acc[u][1] = make_float2(0.f,0.f); }

    for (int k0 = 0; k0 < DH; k0 += 16) {
        __syncthreads();
        #pragma unroll
        for (int p = 0; p < 4; ++p) {
            int idx = tid + p*256;
            int kk = idx & 15, r = idx >> 4;
            float v = g_Q[(h*SQ + i0 + r)*DH + k0 + kk];
            A2[kk*65 + r] = make_float2(v, v);
        }
        #pragma unroll
        for (int p = 0; p < 4; ++p) {
            int idx = tid + p*256;
            int kk = idx & 15, jj = idx >> 4;
            Bs[kk*66 + jj] = g_K[(h*SQ + j0 + jj)*DH + k0 + kk];
        }
        __syncthreads();
        #pragma unroll
        for (int kk = 0; kk < 16; ++kk) {
            float2 b0 = *(const float2*)&Bs[kk*66 + ix*4];
            float2 b1 = *(const float2*)&Bs[kk*66 + ix*4 + 2];
            #pragma unroll
            for (int u = 0; u < 4; ++u) {
                float2 a = A2[kk*65 + iy*4 + u];
                acc[u][0] = ffma2(a, b0, acc[u][0]);
                acc[u][1] = ffma2(a, b1, acc[u][1]);
            }
        }
    }
    #pragma unroll
    for (int u = 0; u < 4; ++u) {
        float* o = g_C2C + ((size_t)h*SQ + i0 + iy*4 + u)*SQ + j0 + ix*4;
        *(float2*)o       = acc[u][0];
        *(float2*)(o + 2) = acc[u][1];
    }
}

// ================= K3: pos contraction on tensor cores (tf32) =============
// CTA i: OUT[i][c][j] = sum_e qkW[i][c][e] * pos[i][j][e]
// mma.m16n8k8.row.col: M=j, N=c, K=e. A=pos[j][e] (row-major), B^T=qkW[c][e].
#define JP 392                      // As pitch (392 % 32 == 8 -> conflict-free frags)
#define NCH 96                      // 768 / 8

__global__ void __launch_bounds__(256) k3_pos(const float* __restrict__ pos)
{
    __shared__ float As[2*8*JP];    // transposed pos chunk: [buf][e(8)][j(384)]
    __shared__ float Bsc[2][192];   // qkW chunk: [buf][c(24)][e(8)]
    int i = blockIdx.x;
    int tid = threadIdx.x;
    int warp = tid >> 5, lane = tid & 31;
    int gid = lane >> 2, tig = lane & 3;
    int j0w = warp * 48;

    const float* posi = pos + (size_t)i * (SQ*HDIM);
    const float* wsrc = g_qkW + (size_t)i * QKW_I_STRIDE;

    float acc[3][3][4];
    #pragma unroll
    for (int jt = 0; jt < 3; ++jt)
        #pragma unroll
        for (int ct = 0; ct < 3; ++ct)
            #pragma unroll
            for (int r = 0; r < 4; ++r) acc[jt][ct][r] = 0.f;

    float4 ra[3];
    float  rb = 0.f;

    // ---- prologue: chunk 0 ----
    #pragma unroll
    for (int p = 0; p < 3; ++p) {
        int idx = tid + p*256;
        int j = idx >> 1, q4 = idx & 1;
        ra[p] = *(const float4*)(posi + (size_t)j*HDIM + q4*4);
    }
    if (tid < 192) rb = wsrc[(tid >> 3)*HDIM + (tid & 7)];
    #pragma unroll
    for (int p = 0; p < 3; ++p) {
        int idx = tid + p*256;
        int j = idx >> 1, eb = (idx & 1)*4;
        As[(eb+0)*JP + j] = ra[p].x;
        As[(eb+1)*JP + j] = ra[p].y;
        As[(eb+2)*JP + j] = ra[p].z;
        As[(eb+3)*JP + j] = ra[p].w;
    }
    if (tid < 192) Bsc[0][tid] = rb;
    __syncthreads();

    for (int ch = 0; ch < NCH; ++ch) {
        int cur = ch & 1, nxt = cur ^ 1;
        if (ch + 1 < NCH) {
            int e0 = (ch + 1) * 8;
            #pragma unroll
            for (int p = 0; p < 3; ++p) {
                int idx = tid + p*256;
                int j = idx >> 1, q4 = idx & 1;
                ra[p] = *(const float4*)(posi + (size_t)j*HDIM + e0 + q4*4);
            }
            if (tid < 192) rb = wsrc[(tid >> 3)*HDIM + e0 + (tid & 7)];
        }
        // ---- compute on cur ----
        {
            const float* a = As + cur*(8*JP);
            const float* b = Bsc[cur];
            unsigned bf[3][2];
            #pragma unroll
            for (int ct = 0; ct < 3; ++ct) {
                bf[ct][0] = __float_as_uint(b[(ct*8 + gid)*8 + tig]);
                bf[ct][1] = __float_as_uint(b[(ct*8 + gid)*8 + tig + 4]);
            }
            #pragma unroll
            for (int jt = 0; jt < 3; ++jt) {
                int j = j0w + jt*16 + gid;
                unsigned a0 = __float_as_uint(a[ tig   *JP + j    ]);
                unsigned a1 = __float_as_uint(a[ tig   *JP + j + 8]);
                unsigned a2 = __float_as_uint(a[(tig+4)*JP + j    ]);
                unsigned a3 = __float_as_uint(a[(tig+4)*JP + j + 8]);
                #pragma unroll
                for (int ct = 0; ct < 3; ++ct)
                    mma_tf32(acc[jt][ct], a0, a1, a2, a3, bf[ct][0], bf[ct][1]);
            }
        }
        // ---- stage next ----
        if (ch + 1 < NCH) {
            float* an = As + nxt*(8*JP);
            #pragma unroll
            for (int p = 0; p < 3; ++p) {
                int idx = tid + p*256;
                int j = idx >> 1, eb = (idx & 1)*4;
                an[(eb+0)*JP + j] = ra[p].x;
                an[(eb+1)*JP + j] = ra[p].y;
                an[(eb+2)*JP + j] = ra[p].z;
                an[(eb+3)*JP + j] = ra[p].w;
            }
            if (tid < 192) Bsc[nxt][tid] = rb;
        }
        __syncthreads();
    }

    // ---- epilogue: stage through smem for coalesced STG ----
    // pass 0: c-tiles 0,1 (c 0..15) -> As[0 .. 16*JP)
    // pass 1: c-tile 2   (c 16..23)
    float* o_base = g_OUT + (size_t)i * OUT_I_STRIDE;
    // pass 0
    #pragma unroll
    for (int jt = 0; jt < 3; ++jt) {
        #pragma unroll
        for (int ct = 0; ct < 2; ++ct) {
            int jj = j0w + jt*16 + gid;
            int cc = ct*8 + tig*2;
            As[ cc   *JP + jj    ] = acc[jt][ct][0];
            As[(cc+1)*JP + jj    ] = acc[jt][ct][1];
            As[ cc   *JP + jj + 8] = acc[jt][ct][2];
            As[(cc+1)*JP + jj + 8] = acc[jt][ct][3];
        }
    }
    __syncthreads();
    #pragma unroll
    for (int p = 0; p < 6; ++p) {
        int idx = tid + p*256;          // 1536 float4
        int cc = idx / 96, j4 = (idx % 96)*4;
        float4 v = *(const float4*)&As[cc*JP + j4];
        *(float4*)(o_base + cc*SQ + j4) = v;
    }
    __syncthreads();
    // pass 1
    #pragma unroll
    for (int jt = 0; jt < 3; ++jt) {
        int jj = j0w + jt*16 + gid;
        int cc = tig*2;
        As[ cc   *JP + jj    ] = acc[jt][2][0];
        As[(cc+1)*JP + jj    ] = acc[jt][2][1];
        As[ cc   *JP + jj + 8] = acc[jt][2][2];
        As[(cc+1)*JP + jj + 8] = acc[jt][2][3];
    }
    __syncthreads();
    #pragma unroll
    for (int p = 0; p < 3; ++p) {
        int idx = tid + p*256;          // 768 float4
        int cc = idx / 96, j4 = (idx % 96)*4;
        float4 v = *(const float4*)&As[cc*JP + j4];
        *(float4*)(o_base + (16 + cc)*SQ + j4) = v;
    }
}

// ================= K3b: assemble scores (incl. p2c transpose) =============
__global__ void k3b_scores(const float* __restrict__ mask)
{
    __shared__ float sh[32*33];
    int h  = blockIdx.z;
    int i0 = blockIdx.y * 32;
    int j0 = blockIdx.x * 32;
    int tid = threadIdx.x;
    #pragma unroll
    for (int p = 0; p < 4; ++p) {
        int idx = tid + p*256;
        int ti = idx & 31, tj = idx >> 5;
        sh[tj*33 + ti] = g_OUT[(size_t)(j0 + tj)*OUT_I_STRIDE + (12 + h)*SQ + i0 + ti];
    }
    __syncthreads();
    #pragma unroll
    for (int p = 0; p < 4; ++p) {
        int idx = tid + p*256;
        int jj = idx & 31, ii = idx >> 5;
        int i = i0 + ii, j = j0 + jj;
        float v = g_C2C[((size_t)h*SQ + i)*SQ + j]
                + g_OUT[(size_t)i*OUT_I_STRIDE + h*SQ + j]
                + sh[jj*33 + ii]
                + g_kb[h*SQ + j];
        g_S[((size_t)h*SQ + i)*SQ + j] = v * 0.125f + mask[j];
    }
}

// ================= K4: softmax ============================================
__global__ void k4_softmax()
{
    __shared__ float red[4];
    int row = blockIdx.x;
    int tid = threadIdx.x;
    const float* s = g_S + (size_t)row*SQ;
    float x0 = s[tid], x1 = s[tid+128], x2 = s[tid+256];
    float m = fmaxf(x0, fmaxf(x1, x2));
    #pragma unroll
    for (int o = 16; o; o >>= 1) m = fmaxf(m, __shfl_xor_sync(0xffffffffu, m, o));
    if ((tid & 31) == 0) red[tid >> 5] = m;
    __syncthreads();
    m = fmaxf(fmaxf(red[0], red[1]), fmaxf(red[2], red[3]));
    float e0 = __expf(x0 - m), e1 = __expf(x1 - m), e2 = __expf(x2 - m);
    float ss = e0 + e1 + e2;
    #pragma unroll
    for (int o = 16; o; o >>= 1) ss += __shfl_xor_sync(0xffffffffu, ss, o);
    __syncthreads();
    if ((tid & 31) == 0) red[tid >> 5] = ss;
    __syncthreads();
    float inv = 1.f / (red[0] + red[1] + red[2] + red[3]);
    float* p = g_P + (size_t)row*SQ;
    p[tid] = e0*inv; p[tid+128] = e1*inv; p[tid+256] = e2*inv;
}

// ================= K5: context = P @ V, write output ======================
__global__ void k5_pv(float* __restrict__ out)
{
    __shared__ float2 A2[16*65];
    __shared__ float  Bs[16*64];
    int h  = blockIdx.y;
    int i0 = blockIdx.x * 64;
    int tid = threadIdx.x;
    int ix = tid & 15, iy = tid >> 4;

    float2 acc[4][2];
    #pragma unroll
    for (int u = 0; u < 4; ++u) { acc[u][0] = make_float2(0.f,0.f); acc[u][1] = make_float2(0.f,0.f); }

    for (int k0 = 0; k0 < SQ; k0 += 16) {
        __syncthreads();
        #pragma unroll
        for (int p = 0; p < 4; ++p) {
            int idx = tid + p*256;
            int kk = idx & 15, r = idx >> 4;
            float v = g_P[((size_t)h*SQ + i0 + r)*SQ + k0 + kk];
            A2[kk*65 + r] = make_float2(v, v);
        }
        #pragma unroll
        for (int p = 0; p < 4; ++p) {
            int idx = tid + p*256;
            int nn = idx & 63, kk = idx >> 6;
            Bs[kk*64 + nn] = g_V[(h*SQ + k0 + kk)*DH + nn];
        }
        __syncthreads();
        #pragma unroll
        for (int kk = 0; kk < 16; ++kk) {
            float2 b0 = *(const float2*)&Bs[kk*64 + ix*4];
            float2 b1 = *(const float2*)&Bs[kk*64 + ix*4 + 2];
            #pragma unroll
            for (int u = 0; u < 4; ++u) {
                float2 a = A2[kk*65 + iy*4 + u];
                acc[u][0] = ffma2(a, b0, acc[u][0]);
                acc[u][1] = ffma2(a, b1, acc[u][1]);
            }
        }
    }
    #pragma unroll
    for (int u = 0; u < 4; ++u) {
        int i = i0 + iy*4 + u;
        float* o = out + (size_t)i*HDIM + h*64 + ix*4;
        *(float2*)o       = acc[u][0];
        *(float2*)(o + 2) = acc[u][1];
    }
}

// ================= launch =================================================
extern "C" void kernel_launch(void* const* d_in, const int* in_sizes, int n_in,
                              void* d_out, int out_size)
{
    const float* hidden = (const float*)d_in[0];
    const float* mask   = (const float*)d_in[1];
    const float* pos    = (const float*)d_in[2];
    const float* Wq  = (const float*)d_in[3];
    const float* bq  = (const float*)d_in[4];
    const float* Wk  = (const float*)d_in[5];
    const float* bk  = (const float*)d_in[6];
    const float* Wv  = (const float*)d_in[7];
    const float* bv  = (const float*)d_in[8];
    const float* Wpk = (const float*)d_in[9];
    // d_in[10] = bpk: constant over j -> softmax-invariant -> exactly cancels
    const float* Wpq = (const float*)d_in[11];
    const float* bpq = (const float*)d_in[12];
    float* out = (float*)d_out;

    // Order puts k3_pos at launch #4 so the fixed ncu sample index lands on it.
    k1_qkv<<<dim3(12, 6, 3), 256>>>(hidden, Wq, bq, Wk, bk, Wv, bv);
    k2_qkw<<<dim3(12, 12, 24), 256>>>(Wpk, Wpq);
    k1b_kb<<<12, 384>>>(bpq);
    k3_pos<<<384, 256>>>(pos);
    k2b_c2c<<<dim3(6, 6, 12), 256>>>();
    k3b_scores<<<dim3(12, 12, 12), 256>>>(mask);
    k4_softmax<<<12*SQ, 128>>>();
    k5_pv<<<dim3(6, 12), 256>>>(out);
}